// round 2
// baseline (speedup 1.0000x reference)
#include <cuda_runtime.h>
#include <math.h>

// ---------------------------------------------------------------------------
// Problem constants
// ---------------------------------------------------------------------------
#define BB 16
#define RR 1024
#define TT 512
#define DD 1024

// GEMM tiling
#define BM 128
#define BN 64
#define BK 16
#define TM 8
#define TN 4
// threads per block = (BM/TM)*(BN/TN) = 16*16 = 256

// ---------------------------------------------------------------------------
// Scratch (static device arrays — no runtime allocation allowed)
// ---------------------------------------------------------------------------
__device__ float g_M[DD * DD];            //  4 MB  M = Wr @ Wq^T
__device__ float g_N[BB * DD * TT];       // 32 MB  N[b,d,t] = sum_e M[d,e] qe[b,t,e]
__device__ float g_S[BB * RR * TT];       // 32 MB  scores
__device__ float g_H[BB * RR * TT];       // 32 MB  h = (rf .* Ws3) @ qe^T
__device__ float g_w2[DD];                // Wq @ br
__device__ float g_c[BB * TT];            // qe . w2   (score bias varying over t)
__device__ float g_e[BB * TT];            // qe . Ws2
__device__ float g_f[BB * RR];            // rf . Ws1

// ---------------------------------------------------------------------------
// Generic NT GEMM: C[M,N] = A[M,K] * B[N,K]^T   (row-major, lda=ldb=K, ldc=N)
// batched via blockIdx.z with element strides.
// ---------------------------------------------------------------------------
__global__ __launch_bounds__(256)
void gemm_nt(const float* __restrict__ A, const float* __restrict__ B,
             float* __restrict__ C, int M, int N, int K,
             long long sA, long long sB, long long sC) {
    A += (long long)blockIdx.z * sA;
    B += (long long)blockIdx.z * sB;
    C += (long long)blockIdx.z * sC;

    __shared__ float As[BK][BM];
    __shared__ float Bs[BK][BN];

    const int tid  = threadIdx.x;
    const int row0 = blockIdx.y * BM;
    const int col0 = blockIdx.x * BN;
    const int ty   = tid >> 4;   // 0..15
    const int tx   = tid & 15;   // 0..15

    float acc[TM][TN] = {};

    for (int k0 = 0; k0 < K; k0 += BK) {
        // A tile: 128x16 = 512 float4, 2 per thread (store transposed)
        #pragma unroll
        for (int i = 0; i < 2; i++) {
            int f = tid + i * 256;
            int r = f >> 2, q = f & 3;
            float4 v = *(const float4*)(A + (size_t)(row0 + r) * K + k0 + q * 4);
            As[q * 4 + 0][r] = v.x; As[q * 4 + 1][r] = v.y;
            As[q * 4 + 2][r] = v.z; As[q * 4 + 3][r] = v.w;
        }
        // B tile: 64x16 = 256 float4, 1 per thread (store transposed)
        {
            int r = tid >> 2, q = tid & 3;
            float4 v = *(const float4*)(B + (size_t)(col0 + r) * K + k0 + q * 4);
            Bs[q * 4 + 0][r] = v.x; Bs[q * 4 + 1][r] = v.y;
            Bs[q * 4 + 2][r] = v.z; Bs[q * 4 + 3][r] = v.w;
        }
        __syncthreads();

        #pragma unroll
        for (int k = 0; k < BK; k++) {
            float4 a0 = *(float4*)&As[k][ty * TM];
            float4 a1 = *(float4*)&As[k][ty * TM + 4];
            float4 b0 = *(float4*)&Bs[k][tx * TN];
            float a[TM] = {a0.x, a0.y, a0.z, a0.w, a1.x, a1.y, a1.z, a1.w};
            float bb[TN] = {b0.x, b0.y, b0.z, b0.w};
            #pragma unroll
            for (int i = 0; i < TM; i++)
                #pragma unroll
                for (int j = 0; j < TN; j++)
                    acc[i][j] += a[i] * bb[j];
        }
        __syncthreads();
    }

    #pragma unroll
    for (int i = 0; i < TM; i++) {
        int rr = row0 + ty * TM + i;
        *(float4*)&C[(size_t)rr * N + col0 + tx * TN] =
            make_float4(acc[i][0], acc[i][1], acc[i][2], acc[i][3]);
    }
}

// ---------------------------------------------------------------------------
// Fused dual GEMM per batch:
//   S[r,t] = sum_d rf[r,d] * Nm[d,t]              (NN: Nm row-major [D,T])
//   H[r,t] = sum_d rf[r,d] * Ws3[d] * qe[t,d]     (NT: qe row-major [T,D])
// ---------------------------------------------------------------------------
__global__ __launch_bounds__(256)
void gemm_sh(const float* __restrict__ rf, const float* __restrict__ Nm,
             const float* __restrict__ qe, const float* __restrict__ Ws3,
             float* __restrict__ S, float* __restrict__ H) {
    const int b = blockIdx.z;
    const float* A  = rf + (size_t)b * RR * DD;
    const float* B1 = Nm + (size_t)b * DD * TT;
    const float* B2 = qe + (size_t)b * TT * DD;
    float* Sb = S + (size_t)b * RR * TT;
    float* Hb = H + (size_t)b * RR * TT;

    __shared__ float As[BK][BM];
    __shared__ float B1s[BK][BN];
    __shared__ float B2s[BK][BN];
    __shared__ float ws[BK];

    const int tid  = threadIdx.x;
    const int row0 = blockIdx.y * BM;
    const int col0 = blockIdx.x * BN;
    const int ty   = tid >> 4;
    const int tx   = tid & 15;

    float accS[TM][TN] = {};
    float accH[TM][TN] = {};

    for (int k0 = 0; k0 < DD; k0 += BK) {
        #pragma unroll
        for (int i = 0; i < 2; i++) {
            int f = tid + i * 256;
            int r = f >> 2, q = f & 3;
            float4 v = *(const float4*)(A + (size_t)(row0 + r) * DD + k0 + q * 4);
            As[q * 4 + 0][r] = v.x; As[q * 4 + 1][r] = v.y;
            As[q * 4 + 2][r] = v.z; As[q * 4 + 3][r] = v.w;
        }
        {   // B1: rows of Nm (k), contiguous over t -> direct [k][n] layout
            int r = tid >> 4, c4 = tid & 15;
            float4 v = *(const float4*)(B1 + (size_t)(k0 + r) * TT + col0 + c4 * 4);
            *(float4*)&B1s[r][c4 * 4] = v;
        }
        {   // B2: NT style (transpose on store)
            int r = tid >> 2, q = tid & 3;
            float4 v = *(const float4*)(B2 + (size_t)(col0 + r) * DD + k0 + q * 4);
            B2s[q * 4 + 0][r] = v.x; B2s[q * 4 + 1][r] = v.y;
            B2s[q * 4 + 2][r] = v.z; B2s[q * 4 + 3][r] = v.w;
        }
        if (tid < 4) *(float4*)&ws[tid * 4] = *(const float4*)(Ws3 + k0 + tid * 4);
        __syncthreads();

        #pragma unroll
        for (int k = 0; k < BK; k++) {
            float4 a0 = *(float4*)&As[k][ty * TM];
            float4 a1 = *(float4*)&As[k][ty * TM + 4];
            float4 v1 = *(float4*)&B1s[k][tx * TN];
            float4 v2 = *(float4*)&B2s[k][tx * TN];
            float w = ws[k];
            float a[TM]  = {a0.x, a0.y, a0.z, a0.w, a1.x, a1.y, a1.z, a1.w};
            float b1[TN] = {v1.x, v1.y, v1.z, v1.w};
            float b2[TN] = {v2.x, v2.y, v2.z, v2.w};
            #pragma unroll
            for (int i = 0; i < TM; i++) {
                float aw = a[i] * w;
                #pragma unroll
                for (int j = 0; j < TN; j++) {
                    accS[i][j] += a[i] * b1[j];
                    accH[i][j] += aw   * b2[j];
                }
            }
        }
        __syncthreads();
    }

    #pragma unroll
    for (int i = 0; i < TM; i++) {
        int rr = row0 + ty * TM + i;
        *(float4*)&Sb[(size_t)rr * TT + col0 + tx * TN] =
            make_float4(accS[i][0], accS[i][1], accS[i][2], accS[i][3]);
        *(float4*)&Hb[(size_t)rr * TT + col0 + tx * TN] =
            make_float4(accH[i][0], accH[i][1], accH[i][2], accH[i][3]);
    }
}

// ---------------------------------------------------------------------------
// w2[d] = sum_h Wq[d,h] * br[h]     (one warp per d)
// ---------------------------------------------------------------------------
__global__ void w2_kernel(const float* __restrict__ Wq, const float* __restrict__ br,
                          float* __restrict__ w2) {
    int warp = (blockIdx.x * blockDim.x + threadIdx.x) >> 5;
    int lane = threadIdx.x & 31;
    if (warp >= DD) return;
    const float* row = Wq + (size_t)warp * DD;
    float s = 0.f;
    for (int h = lane; h < DD; h += 32) s += row[h] * br[h];
    #pragma unroll
    for (int o = 16; o; o >>= 1) s += __shfl_xor_sync(0xffffffffu, s, o);
    if (lane == 0) w2[warp] = s;
}

// ---------------------------------------------------------------------------
// c[b,t] = qe[b,t] . w2 ;  e[b,t] = qe[b,t] . Ws2   (one warp per (b,t))
// ---------------------------------------------------------------------------
__global__ void ce_kernel(const float* __restrict__ qe, const float* __restrict__ w2,
                          const float* __restrict__ Ws2,
                          float* __restrict__ c, float* __restrict__ e) {
    int warp = (blockIdx.x * blockDim.x + threadIdx.x) >> 5;
    int lane = threadIdx.x & 31;
    if (warp >= BB * TT) return;
    const float* row = qe + (size_t)warp * DD;
    float sc = 0.f, se = 0.f;
    for (int d = lane; d < DD; d += 32) {
        float q = row[d];
        sc += q * w2[d];
        se += q * Ws2[d];
    }
    #pragma unroll
    for (int o = 16; o; o >>= 1) {
        sc += __shfl_xor_sync(0xffffffffu, sc, o);
        se += __shfl_xor_sync(0xffffffffu, se, o);
    }
    if (lane == 0) { c[warp] = sc; e[warp] = se; }
}

// ---------------------------------------------------------------------------
// f[b,r] = rf[b,r] . Ws1   (one warp per (b,r))
// ---------------------------------------------------------------------------
__global__ void f_kernel(const float* __restrict__ rf, const float* __restrict__ Ws1,
                         float* __restrict__ f) {
    int warp = (blockIdx.x * blockDim.x + threadIdx.x) >> 5;
    int lane = threadIdx.x & 31;
    if (warp >= BB * RR) return;
    const float* row = rf + (size_t)warp * DD;
    float s = 0.f;
    for (int d = lane; d < DD; d += 32) s += row[d] * Ws1[d];
    #pragma unroll
    for (int o = 16; o; o >>= 1) s += __shfl_xor_sync(0xffffffffu, s, o);
    if (lane == 0) f[warp] = s;
}

// ---------------------------------------------------------------------------
// Per (b,r): softmax over T of (S + c), then out = sum attn*(e + H) + f + bs
// ---------------------------------------------------------------------------
__global__ __launch_bounds__(256)
void finalize_kernel(const float* __restrict__ S, const float* __restrict__ Hm,
                     const float* __restrict__ c, const float* __restrict__ e,
                     const float* __restrict__ f, const float* __restrict__ bs,
                     float* __restrict__ out) {
    const int idx = blockIdx.x;            // b*R + r
    const int b   = idx >> 10;             // / RR
    const float* Srow = S  + (size_t)idx * TT;
    const float* Hrow = Hm + (size_t)idx * TT;
    const float* cb   = c + b * TT;
    const float* eb   = e + b * TT;
    const int tid = threadIdx.x;           // 256

    __shared__ float red[8];
    __shared__ float rs[8], ra[8];

    float m = -1e30f;
    for (int i = tid; i < TT; i += 256) m = fmaxf(m, Srow[i] + cb[i]);
    #pragma unroll
    for (int o = 16; o; o >>= 1) m = fmaxf(m, __shfl_xor_sync(0xffffffffu, m, o));
    if ((tid & 31) == 0) red[tid >> 5] = m;
    __syncthreads();
    if (tid < 8) {
        float v = red[tid];
        #pragma unroll
        for (int o = 4; o; o >>= 1) v = fmaxf(v, __shfl_xor_sync(0xffu, v, o));
        if (tid == 0) red[0] = v;
    }
    __syncthreads();
    m = red[0];

    float sum = 0.f, acc = 0.f;
    for (int i = tid; i < TT; i += 256) {
        float w = expf(Srow[i] + cb[i] - m);
        sum += w;
        acc += w * (eb[i] + Hrow[i]);
    }
    #pragma unroll
    for (int o = 16; o; o >>= 1) {
        sum += __shfl_xor_sync(0xffffffffu, sum, o);
        acc += __shfl_xor_sync(0xffffffffu, acc, o);
    }
    if ((tid & 31) == 0) { rs[tid >> 5] = sum; ra[tid >> 5] = acc; }
    __syncthreads();
    if (tid == 0) {
        float s = 0.f, a = 0.f;
        #pragma unroll
        for (int w = 0; w < 8; w++) { s += rs[w]; a += ra[w]; }
        out[idx] = a / s + f[idx] + bs[0];
    }
}

// ---------------------------------------------------------------------------
// Launch
// ---------------------------------------------------------------------------
extern "C" void kernel_launch(void* const* d_in, const int* in_sizes, int n_in,
                              void* d_out, int out_size) {
    const float* rf = (const float*)d_in[0];   // region_feats [B,R,D]
    const float* qe = (const float*)d_in[1];   // query_embs   [B,T,D]
    const float* Wr = (const float*)d_in[2];   // [D,H]
    const float* br = (const float*)d_in[3];   // [H]
    const float* Wq = (const float*)d_in[4];   // [D,H]
    // d_in[5] = bq: softmax-invariant contribution, provably drops out
    const float* Ws = (const float*)d_in[6];   // [3D,1]
    const float* bs = (const float*)d_in[7];   // [1]
    float* out = (float*)d_out;

    float *gM, *gN, *gS, *gH, *gw2, *gc, *ge, *gf;
    cudaGetSymbolAddress((void**)&gM,  g_M);
    cudaGetSymbolAddress((void**)&gN,  g_N);
    cudaGetSymbolAddress((void**)&gS,  g_S);
    cudaGetSymbolAddress((void**)&gH,  g_H);
    cudaGetSymbolAddress((void**)&gw2, g_w2);
    cudaGetSymbolAddress((void**)&gc,  g_c);
    cudaGetSymbolAddress((void**)&ge,  g_e);
    cudaGetSymbolAddress((void**)&gf,  g_f);

    dim3 blk(256);

    // M = Wr @ Wq^T   [D,D], K=H
    gemm_nt<<<dim3(DD / BN, DD / BM, 1), blk>>>(Wr, Wq, gM, DD, DD, DD, 0, 0, 0);

    // small bias/vector terms
    w2_kernel<<<(DD * 32 + 255) / 256, 256>>>(Wq, br, gw2);
    ce_kernel<<<(BB * TT * 32 + 255) / 256, 256>>>(qe, gw2, Ws + DD, gc, ge);
    f_kernel<<<(BB * RR * 32 + 255) / 256, 256>>>(rf, Ws, gf);

    // N[b] = M @ qe[b]^T  -> [D,T] per batch (NT GEMM, A shared across batch)
    gemm_nt<<<dim3(TT / BN, DD / BM, BB), blk>>>(gM, qe, gN, DD, TT, DD,
                                                 0, (long long)TT * DD,
                                                 (long long)DD * TT);

    // S = rf @ N ; H = (rf .* Ws3) @ qe^T   (fused dual GEMM)
    gemm_sh<<<dim3(TT / BN, RR / BM, BB), blk>>>(rf, gN, qe, Ws + 2 * DD, gS, gH);

    // softmax + weighted reduce + bias terms
    finalize_kernel<<<BB * RR, 256>>>(gS, gH, gc, ge, gf, bs, out);
}

// round 5
// speedup vs baseline: 1.9997x; 1.9997x over previous
#include <cuda_runtime.h>
#include <cuda_bf16.h>
#include <math.h>

#define BB 16
#define RR 1024
#define TT 512
#define DD 1024

// ---------------------------------------------------------------------------
// Scratch (static device arrays — no runtime allocation allowed)
// ---------------------------------------------------------------------------
__device__ unsigned short g_Wrh[DD * DD], g_Wrl[DD * DD];
__device__ unsigned short g_Wqh[DD * DD], g_Wql[DD * DD];
__device__ unsigned short g_Mh[DD * DD],  g_Ml[DD * DD];
__device__ unsigned short g_rfh[BB * RR * DD], g_rfl[BB * RR * DD];
__device__ unsigned short g_qeh[BB * TT * DD], g_qel[BB * TT * DD];
__device__ unsigned short g_qwh[BB * TT * DD], g_qwl[BB * TT * DD];
__device__ unsigned short g_Nth[BB * TT * DD], g_Ntl[BB * TT * DD];
__device__ float g_S[BB * RR * TT];       // 32 MB  scores
__device__ float g_H[BB * RR * TT];       // 32 MB  h-term
__device__ float g_w2[DD];
__device__ float g_c[BB * TT];
__device__ float g_e[BB * TT];
__device__ float g_f[BB * RR];

// ---------------------------------------------------------------------------
// fp32 -> (bf16 hi, bf16 lo) split
// ---------------------------------------------------------------------------
__device__ __forceinline__ void sp(float v, unsigned short& h, unsigned short& l) {
    __nv_bfloat16 bh = __float2bfloat16_rn(v);
    float r = v - __bfloat162float(bh);
    __nv_bfloat16 bl = __float2bfloat16_rn(r);
    h = *reinterpret_cast<unsigned short*>(&bh);
    l = *reinterpret_cast<unsigned short*>(&bl);
}

__global__ void split_kernel(const float4* __restrict__ x,
                             ushort4* __restrict__ h, ushort4* __restrict__ l, int n4) {
    int i = blockIdx.x * blockDim.x + threadIdx.x;
    if (i >= n4) return;
    float4 v = x[i];
    ushort4 hh, ll;
    sp(v.x, hh.x, ll.x); sp(v.y, hh.y, ll.y);
    sp(v.z, hh.z, ll.z); sp(v.w, hh.w, ll.w);
    h[i] = hh; l[i] = ll;
}

// qw[b,t,d] = qe[b,t,d] * Ws3[d], split
__global__ void split_qw_kernel(const float4* __restrict__ qe, const float* __restrict__ Ws3,
                                ushort4* __restrict__ h, ushort4* __restrict__ l, int n4) {
    int i = blockIdx.x * blockDim.x + threadIdx.x;
    if (i >= n4) return;
    float4 v = qe[i];
    int d0 = (i * 4) & (DD - 1);
    float4 w = *(const float4*)&Ws3[d0];
    v.x *= w.x; v.y *= w.y; v.z *= w.z; v.w *= w.w;
    ushort4 hh, ll;
    sp(v.x, hh.x, ll.x); sp(v.y, hh.y, ll.y);
    sp(v.z, hh.z, ll.z); sp(v.w, hh.w, ll.w);
    h[i] = hh; l[i] = ll;
}

// ---------------------------------------------------------------------------
// 3-pass split-bf16 NT GEMM on tensor cores.
//   C[M,N] = A[M,K] * B[N,K]^T  computed as Ah*Bh + Ah*Bl + Al*Bh (fp32 accum)
// CTA tile 128x128x32, 8 warps (warp tile 64x32), double-buffered smem.
// mode 0: write fp32 C ; mode 1: write split bf16 pair (Ch, Cl).
// ---------------------------------------------------------------------------
#define MMA_BF16(c, a, b)                                                      \
    asm volatile(                                                              \
        "mma.sync.aligned.m16n8k16.row.col.f32.bf16.bf16.f32 "                 \
        "{%0,%1,%2,%3},{%4,%5,%6,%7},{%8,%9},{%0,%1,%2,%3};"                   \
        : "+f"(c[0]), "+f"(c[1]), "+f"(c[2]), "+f"(c[3])                       \
        : "r"(a[0]), "r"(a[1]), "r"(a[2]), "r"(a[3]), "r"(b[0]), "r"(b[1]))

__global__ __launch_bounds__(256, 1)
void gemm3_nt(const unsigned short* __restrict__ Ah, const unsigned short* __restrict__ Al,
              const unsigned short* __restrict__ Bh, const unsigned short* __restrict__ Bl,
              float* __restrict__ Cf, unsigned short* __restrict__ Ch,
              unsigned short* __restrict__ Cl,
              int Ndim, int K,
              long long sA, long long sB, long long sC, int mode) {
    extern __shared__ unsigned int smw[];
    const int tid = threadIdx.x, lane = tid & 31, warp = tid >> 5;
    const int g = lane >> 2, tq = lane & 3;
    const int wm = warp & 1, wn = warp >> 1;       // warp grid 2 (M) x 4 (N)
    const int row0 = blockIdx.y * 128, col0 = blockIdx.x * 128;
    const long long z = blockIdx.z;

    const unsigned short* pAh = Ah + z * sA;
    const unsigned short* pAl = Al + z * sA;
    const unsigned short* pBh = Bh + z * sB;
    const unsigned short* pBl = Bl + z * sB;

    const int TW = 20, TSZ = 2560, BUF = 10240;   // words (uint = 2 bf16)

    float c[4][4][4];
    #pragma unroll
    for (int i = 0; i < 4; i++)
        #pragma unroll
        for (int j = 0; j < 4; j++)
            #pragma unroll
            for (int q = 0; q < 4; q++) c[i][j][q] = 0.f;

    uint4 st[8];

    // ---- global load into registers ----
    auto LDG = [&](int k0) {
        #pragma unroll
        for (int t = 0; t < 2; t++) {
            int f = tid + t * 256; int r = f >> 2, q = f & 3;
            size_t oa = (size_t)(row0 + r) * K + k0 + q * 8;
            size_t ob = (size_t)(col0 + r) * K + k0 + q * 8;
            st[0 + t] = *(const uint4*)(pAh + oa);
            st[2 + t] = *(const uint4*)(pAl + oa);
            st[4 + t] = *(const uint4*)(pBh + ob);
            st[6 + t] = *(const uint4*)(pBl + ob);
        }
    };
    // ---- store staged registers to smem ----
    auto STS = [&](int buf) {
        unsigned base = buf * BUF;
        #pragma unroll
        for (int t = 0; t < 2; t++) {
            int f = tid + t * 256; int r = f >> 2, q = f & 3;
            unsigned o = r * TW + q * 4;
            *(uint4*)&smw[base + 0 * TSZ + o] = st[0 + t];
            *(uint4*)&smw[base + 1 * TSZ + o] = st[2 + t];
            *(uint4*)&smw[base + 2 * TSZ + o] = st[4 + t];
            *(uint4*)&smw[base + 3 * TSZ + o] = st[6 + t];
        }
    };

    LDG(0); STS(0); __syncthreads();

    const int steps = K >> 5;
    #pragma unroll 1
    for (int kt = 0; kt < steps; kt++) {
        int cur = kt & 1;
        if (kt + 1 < steps) LDG((kt + 1) << 5);
        unsigned base = cur * BUF;

        #pragma unroll
        for (int ks = 0; ks < 2; ks++) {
            unsigned ah[4][4], al[4][4], bh[4][2], bl[4][2];
            #pragma unroll
            for (int i = 0; i < 4; i++) {
                unsigned ro = (wm * 64 + i * 16 + g) * TW + ks * 8 + tq;
                ah[i][0] = smw[base + ro];
                ah[i][1] = smw[base + ro + 8 * TW];
                ah[i][2] = smw[base + ro + 4];
                ah[i][3] = smw[base + ro + 8 * TW + 4];
                al[i][0] = smw[base + TSZ + ro];
                al[i][1] = smw[base + TSZ + ro + 8 * TW];
                al[i][2] = smw[base + TSZ + ro + 4];
                al[i][3] = smw[base + TSZ + ro + 8 * TW + 4];
            }
            #pragma unroll
            for (int j = 0; j < 4; j++) {
                unsigned no = (wn * 32 + j * 8 + g) * TW + ks * 8 + tq;
                bh[j][0] = smw[base + 2 * TSZ + no];
                bh[j][1] = smw[base + 2 * TSZ + no + 4];
                bl[j][0] = smw[base + 3 * TSZ + no];
                bl[j][1] = smw[base + 3 * TSZ + no + 4];
            }
            #pragma unroll
            for (int i = 0; i < 4; i++)
                #pragma unroll
                for (int j = 0; j < 4; j++) {
                    MMA_BF16(c[i][j], ah[i], bh[j]);
                    MMA_BF16(c[i][j], ah[i], bl[j]);
                    MMA_BF16(c[i][j], al[i], bh[j]);
                }
        }
        if (kt + 1 < steps) STS(cur ^ 1);
        __syncthreads();
    }

    // ---- epilogue ----
    #pragma unroll
    for (int i = 0; i < 4; i++)
        #pragma unroll
        for (int j = 0; j < 4; j++) {
            int r  = row0 + wm * 64 + i * 16 + g;
            int cc = col0 + wn * 32 + j * 8 + tq * 2;
            if (mode == 0) {
                float* P = Cf + z * sC;
                *(float2*)&P[(size_t)r * Ndim + cc] = make_float2(c[i][j][0], c[i][j][1]);
                *(float2*)&P[(size_t)(r + 8) * Ndim + cc] = make_float2(c[i][j][2], c[i][j][3]);
            } else {
                unsigned short* PH = Ch + z * sC;
                unsigned short* PL = Cl + z * sC;
                unsigned short h0, l0, h1, l1;
                sp(c[i][j][0], h0, l0); sp(c[i][j][1], h1, l1);
                *(ushort2*)&PH[(size_t)r * Ndim + cc] = make_ushort2(h0, h1);
                *(ushort2*)&PL[(size_t)r * Ndim + cc] = make_ushort2(l0, l1);
                sp(c[i][j][2], h0, l0); sp(c[i][j][3], h1, l1);
                *(ushort2*)&PH[(size_t)(r + 8) * Ndim + cc] = make_ushort2(h0, h1);
                *(ushort2*)&PL[(size_t)(r + 8) * Ndim + cc] = make_ushort2(l0, l1);
            }
        }
}

// ---------------------------------------------------------------------------
// Small fp32 helper kernels
// ---------------------------------------------------------------------------
__global__ void w2_kernel(const float* __restrict__ Wq, const float* __restrict__ br,
                          float* __restrict__ w2) {
    int warp = (blockIdx.x * blockDim.x + threadIdx.x) >> 5;
    int lane = threadIdx.x & 31;
    if (warp >= DD) return;
    const float* row = Wq + (size_t)warp * DD;
    float s = 0.f;
    for (int h = lane; h < DD; h += 32) s += row[h] * br[h];
    #pragma unroll
    for (int o = 16; o; o >>= 1) s += __shfl_xor_sync(0xffffffffu, s, o);
    if (lane == 0) w2[warp] = s;
}

__global__ void ce_kernel(const float* __restrict__ qe, const float* __restrict__ w2,
                          const float* __restrict__ Ws2,
                          float* __restrict__ c, float* __restrict__ e) {
    int warp = (blockIdx.x * blockDim.x + threadIdx.x) >> 5;
    int lane = threadIdx.x & 31;
    if (warp >= BB * TT) return;
    const float* row = qe + (size_t)warp * DD;
    float sc = 0.f, se = 0.f;
    for (int d = lane; d < DD; d += 32) {
        float q = row[d];
        sc += q * w2[d];
        se += q * Ws2[d];
    }
    #pragma unroll
    for (int o = 16; o; o >>= 1) {
        sc += __shfl_xor_sync(0xffffffffu, sc, o);
        se += __shfl_xor_sync(0xffffffffu, se, o);
    }
    if (lane == 0) { c[warp] = sc; e[warp] = se; }
}

__global__ void f_kernel(const float* __restrict__ rf, const float* __restrict__ Ws1,
                         float* __restrict__ f) {
    int warp = (blockIdx.x * blockDim.x + threadIdx.x) >> 5;
    int lane = threadIdx.x & 31;
    if (warp >= BB * RR) return;
    const float* row = rf + (size_t)warp * DD;
    float s = 0.f;
    for (int d = lane; d < DD; d += 32) s += row[d] * Ws1[d];
    #pragma unroll
    for (int o = 16; o; o >>= 1) s += __shfl_xor_sync(0xffffffffu, s, o);
    if (lane == 0) f[warp] = s;
}

__global__ __launch_bounds__(256)
void finalize_kernel(const float* __restrict__ S, const float* __restrict__ Hm,
                     const float* __restrict__ c, const float* __restrict__ e,
                     const float* __restrict__ f, const float* __restrict__ bs,
                     float* __restrict__ out) {
    const int idx = blockIdx.x;            // b*R + r
    const int b   = idx >> 10;
    const float* Srow = S  + (size_t)idx * TT;
    const float* Hrow = Hm + (size_t)idx * TT;
    const float* cb   = c + b * TT;
    const float* eb   = e + b * TT;
    const int tid = threadIdx.x;

    __shared__ float red[8];
    __shared__ float rs[8], ra[8];

    float m = -1e30f;
    for (int i = tid; i < TT; i += 256) m = fmaxf(m, Srow[i] + cb[i]);
    #pragma unroll
    for (int o = 16; o; o >>= 1) m = fmaxf(m, __shfl_xor_sync(0xffffffffu, m, o));
    if ((tid & 31) == 0) red[tid >> 5] = m;
    __syncthreads();
    if (tid < 8) {
        float v = red[tid];
        #pragma unroll
        for (int o = 4; o; o >>= 1) v = fmaxf(v, __shfl_xor_sync(0xffu, v, o));
        if (tid == 0) red[0] = v;
    }
    __syncthreads();
    m = red[0];

    float sum = 0.f, acc = 0.f;
    for (int i = tid; i < TT; i += 256) {
        float w = expf(Srow[i] + cb[i] - m);
        sum += w;
        acc += w * (eb[i] + Hrow[i]);
    }
    #pragma unroll
    for (int o = 16; o; o >>= 1) {
        sum += __shfl_xor_sync(0xffffffffu, sum, o);
        acc += __shfl_xor_sync(0xffffffffu, acc, o);
    }
    if ((tid & 31) == 0) { rs[tid >> 5] = sum; ra[tid >> 5] = acc; }
    __syncthreads();
    if (tid == 0) {
        float s = 0.f, a = 0.f;
        #pragma unroll
        for (int w = 0; w < 8; w++) { s += rs[w]; a += ra[w]; }
        out[idx] = a / s + f[idx] + bs[0];
    }
}

// ---------------------------------------------------------------------------
// Launch
// ---------------------------------------------------------------------------
extern "C" void kernel_launch(void* const* d_in, const int* in_sizes, int n_in,
                              void* d_out, int out_size) {
    const float* rf = (const float*)d_in[0];   // [B,R,D]
    const float* qe = (const float*)d_in[1];   // [B,T,D]
    const float* Wr = (const float*)d_in[2];   // [D,H]
    const float* br = (const float*)d_in[3];   // [H]
    const float* Wq = (const float*)d_in[4];   // [D,H]
    // d_in[5] = bq: softmax-invariant, provably drops out
    const float* Ws = (const float*)d_in[6];   // [3D,1]
    const float* bs = (const float*)d_in[7];   // [1]
    float* out = (float*)d_out;

    unsigned short *wrh, *wrl, *wqh, *wql, *mh, *ml, *rfh, *rfl, *qeh, *qel,
                   *qwh, *qwl, *nth, *ntl;
    float *gS, *gH, *gw2, *gc, *ge, *gf;
    cudaGetSymbolAddress((void**)&wrh, g_Wrh); cudaGetSymbolAddress((void**)&wrl, g_Wrl);
    cudaGetSymbolAddress((void**)&wqh, g_Wqh); cudaGetSymbolAddress((void**)&wql, g_Wql);
    cudaGetSymbolAddress((void**)&mh,  g_Mh);  cudaGetSymbolAddress((void**)&ml,  g_Ml);
    cudaGetSymbolAddress((void**)&rfh, g_rfh); cudaGetSymbolAddress((void**)&rfl, g_rfl);
    cudaGetSymbolAddress((void**)&qeh, g_qeh); cudaGetSymbolAddress((void**)&qel, g_qel);
    cudaGetSymbolAddress((void**)&qwh, g_qwh); cudaGetSymbolAddress((void**)&qwl, g_qwl);
    cudaGetSymbolAddress((void**)&nth, g_Nth); cudaGetSymbolAddress((void**)&ntl, g_Ntl);
    cudaGetSymbolAddress((void**)&gS,  g_S);   cudaGetSymbolAddress((void**)&gH,  g_H);
    cudaGetSymbolAddress((void**)&gw2, g_w2);  cudaGetSymbolAddress((void**)&gc,  g_c);
    cudaGetSymbolAddress((void**)&ge,  g_e);   cudaGetSymbolAddress((void**)&gf,  g_f);

    cudaFuncSetAttribute(gemm3_nt, cudaFuncAttributeMaxDynamicSharedMemorySize, 81920);

    // ---- splits ----
    {
        int n4 = DD * DD / 4;
        split_kernel<<<(n4 + 255) / 256, 256>>>((const float4*)Wr, (ushort4*)wrh, (ushort4*)wrl, n4);
        split_kernel<<<(n4 + 255) / 256, 256>>>((const float4*)Wq, (ushort4*)wqh, (ushort4*)wql, n4);
    }
    {
        int n4 = BB * RR * DD / 4;
        split_kernel<<<(n4 + 255) / 256, 256>>>((const float4*)rf, (ushort4*)rfh, (ushort4*)rfl, n4);
    }
    {
        int n4 = BB * TT * DD / 4;
        split_kernel<<<(n4 + 255) / 256, 256>>>((const float4*)qe, (ushort4*)qeh, (ushort4*)qel, n4);
        split_qw_kernel<<<(n4 + 255) / 256, 256>>>((const float4*)qe, Ws + 2 * DD,
                                                   (ushort4*)qwh, (ushort4*)qwl, n4);
    }

    // ---- small bias/vector terms (fp32) ----
    w2_kernel<<<(DD * 32 + 255) / 256, 256>>>(Wq, br, gw2);
    ce_kernel<<<(BB * TT * 32 + 255) / 256, 256>>>(qe, gw2, Ws + DD, gc, ge);
    f_kernel<<<(BB * RR * 32 + 255) / 256, 256>>>(rf, Ws, gf);

    // ---- M = Wr @ Wq^T  -> split bf16 (mode 1, single "batch") ----
    gemm3_nt<<<dim3(DD / 128, DD / 128, 1), 256, 81920>>>(
        wrh, wrl, wqh, wql, nullptr, mh, ml, DD, DD, 0, 0, 0, 1);

    // ---- Nt[b] = qe[b] @ M^T -> split bf16 [T,D] directly (no transpose) ----
    gemm3_nt<<<dim3(DD / 128, TT / 128, BB), 256, 81920>>>(
        qeh, qel, mh, ml, nullptr, nth, ntl, DD, DD,
        (long long)TT * DD, 0, (long long)TT * DD, 1);

    // ---- S[b] = rf[b] @ Nt[b]^T -> fp32 [R,T] ----
    gemm3_nt<<<dim3(TT / 128, RR / 128, BB), 256, 81920>>>(
        rfh, rfl, nth, ntl, gS, nullptr, nullptr, TT, DD,
        (long long)RR * DD, (long long)TT * DD, (long long)RR * TT, 0);

    // ---- H[b] = rf[b] @ qw[b]^T -> fp32 [R,T] ----
    gemm3_nt<<<dim3(TT / 128, RR / 128, BB), 256, 81920>>>(
        rfh, rfl, qwh, qwl, gH, nullptr, nullptr, TT, DD,
        (long long)RR * DD, (long long)TT * DD, (long long)RR * TT, 0);

    // ---- softmax + weighted reduce + bias terms ----
    finalize_kernel<<<BB * RR, 256>>>(gS, gH, gc, ge, gf, bs, out);
}